// round 13
// baseline (speedup 1.0000x reference)
#include <cuda_runtime.h>

#define BB 8
#define LL 32768
#define DD 128
#define NTOK (BB * LL)
#define TILE 2048
#define NTILES (NTOK / TILE)
#define MTILE 512                 // merge-round outputs per block
#define MBLOCKS (NTOK / MTILE)    // 512 blocks per merge round

__device__ ulonglong2 g_items[NTOK];
__device__ ulonglong2 g_items2[NTOK];  // ping-pong buffer for merge rounds
__device__ int g_inv[NTOK];            // source row -> final position

__device__ __forceinline__ unsigned int fmono(float f) {
    unsigned int b = __float_as_uint(f);
    return (b & 0x80000000u) ? ~b : (b | 0x80000000u);
}
__device__ __forceinline__ bool item_gt(const ulonglong2& a, const ulonglong2& b) {
    return (a.x > b.x) || (a.x == b.x && a.y > b.y);
}
__device__ __forceinline__ ulonglong2 shfl_item(ulonglong2 v, int m) {
    ulonglong2 o;
    o.x = __shfl_xor_sync(0xffffffffu, v.x, m);
    o.y = __shfl_xor_sync(0xffffffffu, v.y, m);
    return o;
}

// ---------------------------------------------------------------------------
// Key kernel — rounding model LOCKED (R5/R6 bit-exact, C_A): 4 interleaved
// FMA accumulators (u = d mod 4), ascending d, combine (a0+a1)+(a2+a3);
// key = (k0 + 2*k1) + 4*k2. smem-staged coalesced loads (R9 lesson: never
// per-lane row reads).
// ---------------------------------------------------------------------------
__global__ void __launch_bounds__(128) key_kernel(const float* __restrict__ pts,
                                                  const float* __restrict__ alpha) {
    __shared__ float sal[DD * 3];
    __shared__ float tile[128][33];
    int tid = threadIdx.x;
    size_t base = (size_t)blockIdx.x * 128;

    for (int i = tid; i < DD * 3; i += 128) sal[i] = alpha[i];

    float a[3][4];
#pragma unroll
    for (int h = 0; h < 3; h++)
#pragma unroll
        for (int u = 0; u < 4; u++) a[h][u] = 0.f;
    float sq = 0.f;

#pragma unroll
    for (int c = 0; c < 4; c++) {
        __syncthreads();
#pragma unroll
        for (int q = tid; q < 1024; q += 128) {
            int tok = q >> 3, v = q & 7;
            float4 f = *reinterpret_cast<const float4*>(
                pts + (base + tok) * DD + c * 32 + v * 4);
            tile[tok][v * 4 + 0] = f.x;
            tile[tok][v * 4 + 1] = f.y;
            tile[tok][v * 4 + 2] = f.z;
            tile[tok][v * 4 + 3] = f.w;
        }
        __syncthreads();
        const float* p = tile[tid];
#pragma unroll
        for (int j = 0; j < 32; j += 4) {
            int d = c * 32 + j;
#pragma unroll
            for (int u = 0; u < 4; u++) {
                float pv = p[j + u];
                a[0][u] = __fmaf_rn(pv, sal[(d + u) * 3 + 0], a[0][u]);
                a[1][u] = __fmaf_rn(pv, sal[(d + u) * 3 + 1], a[1][u]);
                a[2][u] = __fmaf_rn(pv, sal[(d + u) * 3 + 2], a[2][u]);
                sq      = __fmaf_rn(pv, pv, sq);
            }
        }
    }

    float k0 = __fadd_rn(__fadd_rn(a[0][0], a[0][1]), __fadd_rn(a[0][2], a[0][3]));
    float k1 = __fadd_rn(__fadd_rn(a[1][0], a[1][1]), __fadd_rn(a[1][2], a[1][3]));
    float k2 = __fadd_rn(__fadd_rn(a[2][0], a[2][1]), __fadd_rn(a[2][2], a[2][3]));
    float key = __fadd_rn(__fadd_rn(k0, __fmul_rn(2.f, k1)), __fmul_rn(4.f, k2));
    float nrm = __fsqrt_rn(sq);

    int gtok = (int)base + tid;
    ulonglong2 it;
    it.x = ((unsigned long long)fmono(key) << 32) | (unsigned long long)fmono(nrm);
    it.y = (unsigned long long)(gtok & (LL - 1));
    g_items[gtok] = it;
}

// ---------------------------------------------------------------------------
// Stage 1: full bitonic sort of each 2048 tile, final stage forced ASCENDING
// (merge rounds need all runs ascending; network remains a valid sort).
// ---------------------------------------------------------------------------
__global__ void __launch_bounds__(1024) bitonic_shared_first() {
    __shared__ ulonglong2 s[TILE];
    int base = blockIdx.x * TILE;
    int tid  = threadIdx.x;
    ulonglong2 x = g_items[base + tid];
    ulonglong2 y = g_items[base + tid + 1024];

#pragma unroll
    for (int k = 2; k <= 32; k <<= 1) {
        bool asc = (tid & k) == 0;
#pragma unroll
        for (int j = k >> 1; j; j >>= 1) {
            ulonglong2 ox = shfl_item(x, j), oy = shfl_item(y, j);
            bool wmin = ((tid & j) == 0) == asc;
            if (item_gt(x, ox) == wmin) x = ox;
            if (item_gt(y, oy) == wmin) y = oy;
        }
    }

    for (int k = 64; k <= TILE; k <<= 1) {
        s[tid] = x; s[tid + 1024] = y;
        __syncthreads();
        for (int j = k >> 1; j >= 32; j >>= 1) {
            int i = 2 * tid - (tid & (j - 1));
            int l = i + j;
            bool asc = (k == TILE) ? true
                     : ((((unsigned)(base + i) & (LL - 1)) & (unsigned)k) == 0);
            ulonglong2 a = s[i], b = s[l];
            if (item_gt(a, b) == asc) { s[i] = b; s[l] = a; }
            __syncthreads();
        }
        x = s[tid]; y = s[tid + 1024];
        bool ascx = (k == TILE) ? true
                  : ((((unsigned)(base + tid) & (LL - 1)) & (unsigned)k) == 0);
        bool ascy = (k == TILE) ? true
                  : ((((unsigned)(base + tid + 1024) & (LL - 1)) & (unsigned)k) == 0);
#pragma unroll
        for (int j = 16; j; j >>= 1) {
            ulonglong2 ox = shfl_item(x, j), oy = shfl_item(y, j);
            bool wminx = ((tid & j) == 0) == ascx;
            bool wminy = ((tid & j) == 0) == ascy;
            if (item_gt(x, ox) == wminx) x = ox;
            if (item_gt(y, oy) == wminy) y = oy;
        }
    }
    g_items[base + tid] = x;
    g_items[base + tid + 1024] = y;
}

// ---------------------------------------------------------------------------
// Warp-parallel merge-path diagonal search (keys strictly unique).
// ---------------------------------------------------------------------------
__device__ int mp_search_warp(const ulonglong2* __restrict__ A,
                              const ulonglong2* __restrict__ B,
                              int R, int d) {
    int lane = threadIdx.x & 31;
    int lo = max(0, d - R);
    int hi = min(d, R);
    while (hi > lo) {
        int span = hi - lo;              // candidates a in (lo, hi]
        int chunk = (span + 31) >> 5;    // ceil(span/32)
        int a = lo + 1 + lane * chunk;
        bool valid = a <= hi;
        bool p = false;
        if (valid) p = item_gt(B[d - a], A[a - 1]);   // A[a-1] < B[d-a]
        unsigned mt = __ballot_sync(0xffffffffu, valid && p);
        unsigned mf = __ballot_sync(0xffffffffu, valid && !p);
        int nlo = lo, nhi = hi;
        if (mt) { int i = 31 - __clz(mt); nlo = lo + 1 + i * chunk; }
        if (mf) { int i = __ffs(mf) - 1;  nhi = lo + i * chunk; }
        lo = nlo; hi = nhi;
    }
    return lo;
}

// ---------------------------------------------------------------------------
// Merge round: pairs of ascending runs of size R -> runs of 2R.
// MTILE=512 outputs/block, 128 threads, 4 outputs/thread -> 512 blocks
// (R12 lesson: 128-block grids serialize the latency chain; need 3-4
// blocks/SM to overlap). FINAL round writes inverse permutation + index tail.
// ---------------------------------------------------------------------------
template <int FINAL>
__global__ void __launch_bounds__(128) merge_round(int R, int flip,
                                                   float* __restrict__ out,
                                                   int write_idx) {
    __shared__ ulonglong2 sIn[MTILE];
    __shared__ int sPart[2];
    const ulonglong2* __restrict__ src = flip ? g_items2 : g_items;
    ulonglong2* __restrict__ dst = flip ? g_items : g_items2;

    int t = threadIdx.x;
    int blockOut = blockIdx.x * MTILE;
    int pairSize = 2 * R;
    int pairIdx = blockOut / pairSize;
    int o = blockOut & (pairSize - 1);
    const ulonglong2* A = src + (size_t)pairIdx * pairSize;
    const ulonglong2* B = A + R;

    int w = t >> 5;
    if (w == 0) {
        int a0 = mp_search_warp(A, B, R, o);
        if ((t & 31) == 0) sPart[0] = a0;
    } else if (w == 1) {
        int a1 = mp_search_warp(A, B, R, o + MTILE);
        if ((t & 31) == 0) sPart[1] = a1;
    }
    __syncthreads();
    int a0 = sPart[0], a1 = sPart[1];
    int b0 = o - a0;
    int la = a1 - a0, lb = MTILE - la;

    for (int i = t; i < la; i += 128) sIn[i] = A[a0 + i];
    for (int i = t; i < lb; i += 128) sIn[la + i] = B[b0 + i];
    __syncthreads();

    // local partition for this thread's 4 outputs
    int dl = t * 4;
    int alo = max(0, dl - lb), ahi = min(dl, la);
    while (alo < ahi) {
        int mid = (alo + ahi + 1) >> 1;
        if (item_gt(sIn[la + dl - mid], sIn[mid - 1])) alo = mid; else ahi = mid - 1;
    }
    int ai = alo, bi = dl - alo;

    ulonglong2 v[4];
#pragma unroll
    for (int i = 0; i < 4; i++) {
        bool takeA;
        if (ai >= la) takeA = false;
        else if (bi >= lb) takeA = true;
        else takeA = item_gt(sIn[la + bi], sIn[ai]);  // A < B (keys unique)
        v[i] = takeA ? sIn[ai++] : sIn[la + bi++];
    }

    if (FINAL) {
        int batch = blockOut >> 15;
#pragma unroll
        for (int i = 0; i < 4; i++) {
            int e = blockOut + dl + i;
            g_inv[batch * LL + (int)v[i].y] = e;
            if (write_idx) out[(size_t)NTOK * DD + e] = (float)(int)v[i].y;
        }
    } else {
        __syncthreads();
#pragma unroll
        for (int i = 0; i < 4; i++) sIn[dl + i] = v[i];
        __syncthreads();
#pragma unroll
        for (int i = 0; i < 4; i++) {
            int idx = t + i * 128;
            dst[blockOut + idx] = sIn[idx];
        }
    }
}

// ---------------------------------------------------------------------------
// Scatter: linear read of pts (streaming), random full-row write via g_inv.
// One warp per source row (R8-proven pattern).
// ---------------------------------------------------------------------------
__global__ void __launch_bounds__(256) scatter_kernel(const float* __restrict__ pts,
                                                      float* __restrict__ out) {
    int gwarp = (blockIdx.x * blockDim.x + threadIdx.x) >> 5;
    int lane  = threadIdx.x & 31;
    if (gwarp >= NTOK) return;
    int dst = g_inv[gwarp];  // broadcast across warp
    const float4* src = reinterpret_cast<const float4*>(pts + (size_t)gwarp * DD);
    float4* d = reinterpret_cast<float4*>(out + (size_t)dst * DD);
    d[lane] = src[lane];
}

extern "C" void kernel_launch(void* const* d_in, const int* in_sizes, int n_in,
                              void* d_out, int out_size) {
    (void)n_in;
    const float* pts   = (const float*)d_in[0];
    const float* alpha = (const float*)d_in[1];
    if (in_sizes[0] < in_sizes[1]) { pts = (const float*)d_in[1]; alpha = (const float*)d_in[0]; }

    float* out = (float*)d_out;
    int write_idx = (out_size >= NTOK * DD + NTOK) ? 1 : 0;

    key_kernel<<<NTOK / 128, 128>>>(pts, alpha);
    bitonic_shared_first<<<NTILES, 1024>>>();

    merge_round<0><<<MBLOCKS, 128>>>(2048, 0, out, 0);   // items  -> items2
    merge_round<0><<<MBLOCKS, 128>>>(4096, 1, out, 0);   // items2 -> items
    merge_round<0><<<MBLOCKS, 128>>>(8192, 0, out, 0);   // items  -> items2
    merge_round<1><<<MBLOCKS, 128>>>(16384, 1, out, write_idx);  // items2 -> g_inv

    scatter_kernel<<<NTOK / 8, 256>>>(pts, out);
}

// round 14
// speedup vs baseline: 1.0249x; 1.0249x over previous
#include <cuda_runtime.h>

#define BB 8
#define LL 32768
#define DD 128
#define NTOK (BB * LL)
#define TILE 2048
#define NTILES (NTOK / TILE)
#define MTILE 256                 // merge-round outputs per block
#define MBLOCKS (NTOK / MTILE)    // 1024 blocks per merge round

__device__ ulonglong2 g_items[NTOK];
__device__ ulonglong2 g_items2[NTOK];  // ping-pong buffer for merge rounds
__device__ int g_inv[NTOK];            // source row -> final position

__device__ __forceinline__ unsigned int fmono(float f) {
    unsigned int b = __float_as_uint(f);
    return (b & 0x80000000u) ? ~b : (b | 0x80000000u);
}
__device__ __forceinline__ bool item_gt(const ulonglong2& a, const ulonglong2& b) {
    return (a.x > b.x) || (a.x == b.x && a.y > b.y);
}
__device__ __forceinline__ ulonglong2 shfl_item(ulonglong2 v, int m) {
    ulonglong2 o;
    o.x = __shfl_xor_sync(0xffffffffu, v.x, m);
    o.y = __shfl_xor_sync(0xffffffffu, v.y, m);
    return o;
}

// ---------------------------------------------------------------------------
// Key kernel — rounding model LOCKED (R5/R6 bit-exact, C_A): 4 interleaved
// FMA accumulators (u = d mod 4), ascending d, combine (a0+a1)+(a2+a3);
// key = (k0 + 2*k1) + 4*k2. smem-staged coalesced loads (R9 lesson: never
// per-lane row reads).
// ---------------------------------------------------------------------------
__global__ void __launch_bounds__(128) key_kernel(const float* __restrict__ pts,
                                                  const float* __restrict__ alpha) {
    __shared__ float sal[DD * 3];
    __shared__ float tile[128][33];
    int tid = threadIdx.x;
    size_t base = (size_t)blockIdx.x * 128;

    for (int i = tid; i < DD * 3; i += 128) sal[i] = alpha[i];

    float a[3][4];
#pragma unroll
    for (int h = 0; h < 3; h++)
#pragma unroll
        for (int u = 0; u < 4; u++) a[h][u] = 0.f;
    float sq = 0.f;

#pragma unroll
    for (int c = 0; c < 4; c++) {
        __syncthreads();
#pragma unroll
        for (int q = tid; q < 1024; q += 128) {
            int tok = q >> 3, v = q & 7;
            float4 f = *reinterpret_cast<const float4*>(
                pts + (base + tok) * DD + c * 32 + v * 4);
            tile[tok][v * 4 + 0] = f.x;
            tile[tok][v * 4 + 1] = f.y;
            tile[tok][v * 4 + 2] = f.z;
            tile[tok][v * 4 + 3] = f.w;
        }
        __syncthreads();
        const float* p = tile[tid];
#pragma unroll
        for (int j = 0; j < 32; j += 4) {
            int d = c * 32 + j;
#pragma unroll
            for (int u = 0; u < 4; u++) {
                float pv = p[j + u];
                a[0][u] = __fmaf_rn(pv, sal[(d + u) * 3 + 0], a[0][u]);
                a[1][u] = __fmaf_rn(pv, sal[(d + u) * 3 + 1], a[1][u]);
                a[2][u] = __fmaf_rn(pv, sal[(d + u) * 3 + 2], a[2][u]);
                sq      = __fmaf_rn(pv, pv, sq);
            }
        }
    }

    float k0 = __fadd_rn(__fadd_rn(a[0][0], a[0][1]), __fadd_rn(a[0][2], a[0][3]));
    float k1 = __fadd_rn(__fadd_rn(a[1][0], a[1][1]), __fadd_rn(a[1][2], a[1][3]));
    float k2 = __fadd_rn(__fadd_rn(a[2][0], a[2][1]), __fadd_rn(a[2][2], a[2][3]));
    float key = __fadd_rn(__fadd_rn(k0, __fmul_rn(2.f, k1)), __fmul_rn(4.f, k2));
    float nrm = __fsqrt_rn(sq);

    int gtok = (int)base + tid;
    ulonglong2 it;
    it.x = ((unsigned long long)fmono(key) << 32) | (unsigned long long)fmono(nrm);
    it.y = (unsigned long long)(gtok & (LL - 1));
    g_items[gtok] = it;
}

// ---------------------------------------------------------------------------
// Stage 1: full bitonic sort of each 2048 tile, final stage forced ASCENDING
// (merge rounds need all runs ascending; network remains a valid sort).
// ---------------------------------------------------------------------------
__global__ void __launch_bounds__(1024) bitonic_shared_first() {
    __shared__ ulonglong2 s[TILE];
    int base = blockIdx.x * TILE;
    int tid  = threadIdx.x;
    ulonglong2 x = g_items[base + tid];
    ulonglong2 y = g_items[base + tid + 1024];

#pragma unroll
    for (int k = 2; k <= 32; k <<= 1) {
        bool asc = (tid & k) == 0;
#pragma unroll
        for (int j = k >> 1; j; j >>= 1) {
            ulonglong2 ox = shfl_item(x, j), oy = shfl_item(y, j);
            bool wmin = ((tid & j) == 0) == asc;
            if (item_gt(x, ox) == wmin) x = ox;
            if (item_gt(y, oy) == wmin) y = oy;
        }
    }

    for (int k = 64; k <= TILE; k <<= 1) {
        s[tid] = x; s[tid + 1024] = y;
        __syncthreads();
        for (int j = k >> 1; j >= 32; j >>= 1) {
            int i = 2 * tid - (tid & (j - 1));
            int l = i + j;
            bool asc = (k == TILE) ? true
                     : ((((unsigned)(base + i) & (LL - 1)) & (unsigned)k) == 0);
            ulonglong2 a = s[i], b = s[l];
            if (item_gt(a, b) == asc) { s[i] = b; s[l] = a; }
            __syncthreads();
        }
        x = s[tid]; y = s[tid + 1024];
        bool ascx = (k == TILE) ? true
                  : ((((unsigned)(base + tid) & (LL - 1)) & (unsigned)k) == 0);
        bool ascy = (k == TILE) ? true
                  : ((((unsigned)(base + tid + 1024) & (LL - 1)) & (unsigned)k) == 0);
#pragma unroll
        for (int j = 16; j; j >>= 1) {
            ulonglong2 ox = shfl_item(x, j), oy = shfl_item(y, j);
            bool wminx = ((tid & j) == 0) == ascx;
            bool wminy = ((tid & j) == 0) == ascy;
            if (item_gt(x, ox) == wminx) x = ox;
            if (item_gt(y, oy) == wminy) y = oy;
        }
    }
    g_items[base + tid] = x;
    g_items[base + tid + 1024] = y;
}

// ---------------------------------------------------------------------------
// Warp-parallel merge-path diagonal search (keys strictly unique).
// ---------------------------------------------------------------------------
__device__ int mp_search_warp(const ulonglong2* __restrict__ A,
                              const ulonglong2* __restrict__ B,
                              int R, int d) {
    int lane = threadIdx.x & 31;
    int lo = max(0, d - R);
    int hi = min(d, R);
    while (hi > lo) {
        int span = hi - lo;              // candidates a in (lo, hi]
        int chunk = (span + 31) >> 5;    // ceil(span/32)
        int a = lo + 1 + lane * chunk;
        bool valid = a <= hi;
        bool p = false;
        if (valid) p = item_gt(B[d - a], A[a - 1]);   // A[a-1] < B[d-a]
        unsigned mt = __ballot_sync(0xffffffffu, valid && p);
        unsigned mf = __ballot_sync(0xffffffffu, valid && !p);
        int nlo = lo, nhi = hi;
        if (mt) { int i = 31 - __clz(mt); nlo = lo + 1 + i * chunk; }
        if (mf) { int i = __ffs(mf) - 1;  nhi = lo + i * chunk; }
        lo = nlo; hi = nhi;
    }
    return lo;
}

// ---------------------------------------------------------------------------
// Merge round: pairs of ascending runs of size R -> runs of 2R.
// MTILE=256 outputs/block, 256 threads, ONE output/thread -> 8192 warps
// (R13 lesson: occupancy = total warps, not blocks; 4 outputs/thread capped
// us at 2048 warps). Per thread: 8-step smem binary search + single select;
// output write directly coalesced. FINAL: inverse permutation + index tail.
// ---------------------------------------------------------------------------
template <int FINAL>
__global__ void __launch_bounds__(256) merge_round(int R, int flip,
                                                   float* __restrict__ out,
                                                   int write_idx) {
    __shared__ ulonglong2 sIn[MTILE];
    __shared__ int sPart[2];
    const ulonglong2* __restrict__ src = flip ? g_items2 : g_items;
    ulonglong2* __restrict__ dst = flip ? g_items : g_items2;

    int t = threadIdx.x;
    int blockOut = blockIdx.x * MTILE;
    int pairSize = 2 * R;
    int pairIdx = blockOut / pairSize;
    int o = blockOut & (pairSize - 1);
    const ulonglong2* A = src + (size_t)pairIdx * pairSize;
    const ulonglong2* B = A + R;

    int w = t >> 5;
    if (w == 0) {
        int a0 = mp_search_warp(A, B, R, o);
        if ((t & 31) == 0) sPart[0] = a0;
    } else if (w == 1) {
        int a1 = mp_search_warp(A, B, R, o + MTILE);
        if ((t & 31) == 0) sPart[1] = a1;
    }
    __syncthreads();
    int a0 = sPart[0], a1 = sPart[1];
    int b0 = o - a0;
    int la = a1 - a0, lb = MTILE - la;

    if (t < la) sIn[t] = A[a0 + t];
    if (t < lb) sIn[la + t] = B[b0 + t];
    __syncthreads();

    // per-thread partition for its single output (diagonal d = t)
    int dl = t;
    int alo = max(0, dl - lb), ahi = min(dl, la);
    while (alo < ahi) {
        int mid = (alo + ahi + 1) >> 1;
        if (item_gt(sIn[la + dl - mid], sIn[mid - 1])) alo = mid; else ahi = mid - 1;
    }
    int ai = alo, bi = dl - alo;

    bool takeA;
    if (ai >= la) takeA = false;
    else if (bi >= lb) takeA = true;
    else takeA = item_gt(sIn[la + bi], sIn[ai]);  // A < B (keys unique)
    ulonglong2 v = takeA ? sIn[ai] : sIn[la + bi];

    if (FINAL) {
        int batch = blockOut >> 15;
        int e = blockOut + dl;
        g_inv[batch * LL + (int)v.y] = e;
        if (write_idx) out[(size_t)NTOK * DD + e] = (float)(int)v.y;
    } else {
        dst[blockOut + dl] = v;  // coalesced
    }
}

// ---------------------------------------------------------------------------
// Scatter: linear read of pts (streaming), random full-row write via g_inv.
// One warp per source row (R8-proven pattern).
// ---------------------------------------------------------------------------
__global__ void __launch_bounds__(256) scatter_kernel(const float* __restrict__ pts,
                                                      float* __restrict__ out) {
    int gwarp = (blockIdx.x * blockDim.x + threadIdx.x) >> 5;
    int lane  = threadIdx.x & 31;
    if (gwarp >= NTOK) return;
    int dst = g_inv[gwarp];  // broadcast across warp
    const float4* src = reinterpret_cast<const float4*>(pts + (size_t)gwarp * DD);
    float4* d = reinterpret_cast<float4*>(out + (size_t)dst * DD);
    d[lane] = src[lane];
}

extern "C" void kernel_launch(void* const* d_in, const int* in_sizes, int n_in,
                              void* d_out, int out_size) {
    (void)n_in;
    const float* pts   = (const float*)d_in[0];
    const float* alpha = (const float*)d_in[1];
    if (in_sizes[0] < in_sizes[1]) { pts = (const float*)d_in[1]; alpha = (const float*)d_in[0]; }

    float* out = (float*)d_out;
    int write_idx = (out_size >= NTOK * DD + NTOK) ? 1 : 0;

    key_kernel<<<NTOK / 128, 128>>>(pts, alpha);
    bitonic_shared_first<<<NTILES, 1024>>>();

    merge_round<0><<<MBLOCKS, 256>>>(2048, 0, out, 0);   // items  -> items2
    merge_round<0><<<MBLOCKS, 256>>>(4096, 1, out, 0);   // items2 -> items
    merge_round<0><<<MBLOCKS, 256>>>(8192, 0, out, 0);   // items  -> items2
    merge_round<1><<<MBLOCKS, 256>>>(16384, 1, out, write_idx);  // items2 -> g_inv

    scatter_kernel<<<NTOK / 8, 256>>>(pts, out);
}

// round 15
// speedup vs baseline: 1.0622x; 1.0364x over previous
#include <cuda_runtime.h>

#define BB 8
#define LL 32768
#define DD 128
#define NTOK (BB * LL)
#define TILE 2048
#define NTILES (NTOK / TILE)
#define MTILE 256                 // merge-round outputs per block
#define MBLOCKS (NTOK / MTILE)    // 1024 blocks per merge round

__device__ ulonglong2 g_items[NTOK];
__device__ ulonglong2 g_items2[NTOK];  // ping-pong buffer for merge rounds
__device__ int g_inv[NTOK];            // source row -> final position

__device__ __forceinline__ unsigned int fmono(float f) {
    unsigned int b = __float_as_uint(f);
    return (b & 0x80000000u) ? ~b : (b | 0x80000000u);
}
__device__ __forceinline__ bool item_gt(const ulonglong2& a, const ulonglong2& b) {
    return (a.x > b.x) || (a.x == b.x && a.y > b.y);
}
__device__ __forceinline__ ulonglong2 shfl_item(ulonglong2 v, int m) {
    ulonglong2 o;
    o.x = __shfl_xor_sync(0xffffffffu, v.x, m);
    o.y = __shfl_xor_sync(0xffffffffu, v.y, m);
    return o;
}

// ---------------------------------------------------------------------------
// Key kernel — rounding model LOCKED (R5/R6 bit-exact, C_A): 4 interleaved
// FMA accumulators (u = d mod 4), ascending d, combine (a0+a1)+(a2+a3);
// key = (k0 + 2*k1) + 4*k2. smem-staged coalesced loads (R9 lesson: never
// per-lane row reads).
// ---------------------------------------------------------------------------
__global__ void __launch_bounds__(128) key_kernel(const float* __restrict__ pts,
                                                  const float* __restrict__ alpha) {
    __shared__ float sal[DD * 3];
    __shared__ float tile[128][33];
    int tid = threadIdx.x;
    size_t base = (size_t)blockIdx.x * 128;

    for (int i = tid; i < DD * 3; i += 128) sal[i] = alpha[i];

    float a[3][4];
#pragma unroll
    for (int h = 0; h < 3; h++)
#pragma unroll
        for (int u = 0; u < 4; u++) a[h][u] = 0.f;
    float sq = 0.f;

#pragma unroll
    for (int c = 0; c < 4; c++) {
        __syncthreads();
#pragma unroll
        for (int q = tid; q < 1024; q += 128) {
            int tok = q >> 3, v = q & 7;
            float4 f = *reinterpret_cast<const float4*>(
                pts + (base + tok) * DD + c * 32 + v * 4);
            tile[tok][v * 4 + 0] = f.x;
            tile[tok][v * 4 + 1] = f.y;
            tile[tok][v * 4 + 2] = f.z;
            tile[tok][v * 4 + 3] = f.w;
        }
        __syncthreads();
        const float* p = tile[tid];
#pragma unroll
        for (int j = 0; j < 32; j += 4) {
            int d = c * 32 + j;
#pragma unroll
            for (int u = 0; u < 4; u++) {
                float pv = p[j + u];
                a[0][u] = __fmaf_rn(pv, sal[(d + u) * 3 + 0], a[0][u]);
                a[1][u] = __fmaf_rn(pv, sal[(d + u) * 3 + 1], a[1][u]);
                a[2][u] = __fmaf_rn(pv, sal[(d + u) * 3 + 2], a[2][u]);
                sq      = __fmaf_rn(pv, pv, sq);
            }
        }
    }

    float k0 = __fadd_rn(__fadd_rn(a[0][0], a[0][1]), __fadd_rn(a[0][2], a[0][3]));
    float k1 = __fadd_rn(__fadd_rn(a[1][0], a[1][1]), __fadd_rn(a[1][2], a[1][3]));
    float k2 = __fadd_rn(__fadd_rn(a[2][0], a[2][1]), __fadd_rn(a[2][2], a[2][3]));
    float key = __fadd_rn(__fadd_rn(k0, __fmul_rn(2.f, k1)), __fmul_rn(4.f, k2));
    float nrm = __fsqrt_rn(sq);

    int gtok = (int)base + tid;
    ulonglong2 it;
    it.x = ((unsigned long long)fmono(key) << 32) | (unsigned long long)fmono(nrm);
    it.y = (unsigned long long)(gtok & (LL - 1));
    g_items[gtok] = it;
}

// ---------------------------------------------------------------------------
// Stage 1: full bitonic sort of each 2048 tile (full composite compare ->
// equal-key items end up in index order), final stage forced ASCENDING.
// ---------------------------------------------------------------------------
__global__ void __launch_bounds__(1024) bitonic_shared_first() {
    __shared__ ulonglong2 s[TILE];
    int base = blockIdx.x * TILE;
    int tid  = threadIdx.x;
    ulonglong2 x = g_items[base + tid];
    ulonglong2 y = g_items[base + tid + 1024];

#pragma unroll
    for (int k = 2; k <= 32; k <<= 1) {
        bool asc = (tid & k) == 0;
#pragma unroll
        for (int j = k >> 1; j; j >>= 1) {
            ulonglong2 ox = shfl_item(x, j), oy = shfl_item(y, j);
            bool wmin = ((tid & j) == 0) == asc;
            if (item_gt(x, ox) == wmin) x = ox;
            if (item_gt(y, oy) == wmin) y = oy;
        }
    }

    for (int k = 64; k <= TILE; k <<= 1) {
        s[tid] = x; s[tid + 1024] = y;
        __syncthreads();
        for (int j = k >> 1; j >= 32; j >>= 1) {
            int i = 2 * tid - (tid & (j - 1));
            int l = i + j;
            bool asc = (k == TILE) ? true
                     : ((((unsigned)(base + i) & (LL - 1)) & (unsigned)k) == 0);
            ulonglong2 a = s[i], b = s[l];
            if (item_gt(a, b) == asc) { s[i] = b; s[l] = a; }
            __syncthreads();
        }
        x = s[tid]; y = s[tid + 1024];
        bool ascx = (k == TILE) ? true
                  : ((((unsigned)(base + tid) & (LL - 1)) & (unsigned)k) == 0);
        bool ascy = (k == TILE) ? true
                  : ((((unsigned)(base + tid + 1024) & (LL - 1)) & (unsigned)k) == 0);
#pragma unroll
        for (int j = 16; j; j >>= 1) {
            ulonglong2 ox = shfl_item(x, j), oy = shfl_item(y, j);
            bool wminx = ((tid & j) == 0) == ascx;
            bool wminy = ((tid & j) == 0) == ascy;
            if (item_gt(x, ox) == wminx) x = ox;
            if (item_gt(y, oy) == wminy) y = oy;
        }
    }
    g_items[base + tid] = x;
    g_items[base + tid + 1024] = y;
}

// ---------------------------------------------------------------------------
// Warp-parallel merge-path diagonal search, KEY-ONLY + STABLE (A wins ties):
// find max a such that A[a-1].key <= B[d-a].key.
// ---------------------------------------------------------------------------
__device__ int mp_search_warp(const ulonglong2* __restrict__ A,
                              const ulonglong2* __restrict__ B,
                              int R, int d) {
    int lane = threadIdx.x & 31;
    int lo = max(0, d - R);
    int hi = min(d, R);
    while (hi > lo) {
        int span = hi - lo;              // candidates a in (lo, hi]
        int chunk = (span + 31) >> 5;    // ceil(span/32)
        int a = lo + 1 + lane * chunk;
        bool valid = a <= hi;
        bool p = false;
        if (valid) p = (B[d - a].x >= A[a - 1].x);   // A[a-1] <= B[d-a]
        unsigned mt = __ballot_sync(0xffffffffu, valid && p);
        unsigned mf = __ballot_sync(0xffffffffu, valid && !p);
        int nlo = lo, nhi = hi;
        if (mt) { int i = 31 - __clz(mt); nlo = lo + 1 + i * chunk; }
        if (mf) { int i = __ffs(mf) - 1;  nhi = lo + i * chunk; }
        lo = nlo; hi = nhi;
    }
    return lo;
}

// ---------------------------------------------------------------------------
// Merge round: pairs of ascending runs of size R -> runs of 2R.
// MTILE=256 outputs/block, 256 threads, one output/thread. SoA smem:
// sKey (8B) + sIdx (4B) -> search iterations are 2x LDS.64 + one u64 compare
// (R14 lesson: passes are instruction-bound; the 16B lexicographic compare
// was the fat). Stable (A wins ties) => identical permutation to composite
// compare, since runs are index-ordered within equal keys.
// ---------------------------------------------------------------------------
template <int FINAL>
__global__ void __launch_bounds__(256) merge_round(int R, int flip,
                                                   float* __restrict__ out,
                                                   int write_idx) {
    __shared__ unsigned long long sKey[MTILE];
    __shared__ int sIdx[MTILE];
    __shared__ int sPart[2];
    const ulonglong2* __restrict__ src = flip ? g_items2 : g_items;
    ulonglong2* __restrict__ dst = flip ? g_items : g_items2;

    int t = threadIdx.x;
    int blockOut = blockIdx.x * MTILE;
    int pairSize = 2 * R;
    int pairIdx = blockOut / pairSize;
    int o = blockOut & (pairSize - 1);
    const ulonglong2* A = src + (size_t)pairIdx * pairSize;
    const ulonglong2* B = A + R;

    int w = t >> 5;
    if (w == 0) {
        int a0 = mp_search_warp(A, B, R, o);
        if ((t & 31) == 0) sPart[0] = a0;
    } else if (w == 1) {
        int a1 = mp_search_warp(A, B, R, o + MTILE);
        if ((t & 31) == 0) sPart[1] = a1;
    }
    __syncthreads();
    int a0 = sPart[0], a1 = sPart[1];
    int b0 = o - a0;
    int la = a1 - a0, lb = MTILE - la;

    if (t < la) {
        ulonglong2 it = A[a0 + t];
        sKey[t] = it.x; sIdx[t] = (int)it.y;
    }
    if (t < lb) {
        ulonglong2 it = B[b0 + t];
        sKey[la + t] = it.x; sIdx[la + t] = (int)it.y;
    }
    __syncthreads();

    // per-thread partition (diagonal d = t): max ai with A[ai-1] <= B[d-ai]
    int dl = t;
    int alo = max(0, dl - lb), ahi = min(dl, la);
    while (alo < ahi) {
        int mid = (alo + ahi + 1) >> 1;
        if (sKey[la + dl - mid] >= sKey[mid - 1]) alo = mid; else ahi = mid - 1;
    }
    int ai = alo, bi = dl - alo;

    bool takeA = (ai < la) && (bi >= lb || sKey[la + bi] >= sKey[ai]);
    int pos = takeA ? ai : (la + bi);
    unsigned long long vk = sKey[pos];
    int vi = sIdx[pos];

    if (FINAL) {
        int batch = blockOut >> 15;
        int e = blockOut + dl;
        g_inv[batch * LL + vi] = e;
        if (write_idx) out[(size_t)NTOK * DD + e] = (float)vi;
    } else {
        ulonglong2 v;
        v.x = vk; v.y = (unsigned long long)vi;
        dst[blockOut + dl] = v;  // coalesced
    }
}

// ---------------------------------------------------------------------------
// Scatter: linear read of pts (streaming), random full-row write via g_inv.
// One warp per source row (R8-proven pattern).
// ---------------------------------------------------------------------------
__global__ void __launch_bounds__(256) scatter_kernel(const float* __restrict__ pts,
                                                      float* __restrict__ out) {
    int gwarp = (blockIdx.x * blockDim.x + threadIdx.x) >> 5;
    int lane  = threadIdx.x & 31;
    if (gwarp >= NTOK) return;
    int dst = g_inv[gwarp];  // broadcast across warp
    const float4* src = reinterpret_cast<const float4*>(pts + (size_t)gwarp * DD);
    float4* d = reinterpret_cast<float4*>(out + (size_t)dst * DD);
    d[lane] = src[lane];
}

extern "C" void kernel_launch(void* const* d_in, const int* in_sizes, int n_in,
                              void* d_out, int out_size) {
    (void)n_in;
    const float* pts   = (const float*)d_in[0];
    const float* alpha = (const float*)d_in[1];
    if (in_sizes[0] < in_sizes[1]) { pts = (const float*)d_in[1]; alpha = (const float*)d_in[0]; }

    float* out = (float*)d_out;
    int write_idx = (out_size >= NTOK * DD + NTOK) ? 1 : 0;

    key_kernel<<<NTOK / 128, 128>>>(pts, alpha);
    bitonic_shared_first<<<NTILES, 1024>>>();

    merge_round<0><<<MBLOCKS, 256>>>(2048, 0, out, 0);   // items  -> items2
    merge_round<0><<<MBLOCKS, 256>>>(4096, 1, out, 0);   // items2 -> items
    merge_round<0><<<MBLOCKS, 256>>>(8192, 0, out, 0);   // items  -> items2
    merge_round<1><<<MBLOCKS, 256>>>(16384, 1, out, write_idx);  // items2 -> g_inv

    scatter_kernel<<<NTOK / 8, 256>>>(pts, out);
}